// round 1
// baseline (speedup 1.0000x reference)
#include <cuda_runtime.h>
#include <math.h>

#define HD     128
#define HEADS  4
#define CDIM   32
#define NLAYER 4
#define NEG    100
#define HS     128

#define N_MAX  2048
#define E_MAX  4096
#define F_MAX  (N_MAX + E_MAX)

// ---------------- scratch (device globals; no allocation allowed) ----------
__device__ float g_h   [N_MAX * HD];
__device__ float g_e   [E_MAX * HD];
__device__ float g_xl  [N_MAX * HD];
__device__ float g_ssrc[N_MAX * HEADS];
__device__ float g_sdst[N_MAX * HEADS];
__device__ float g_ae  [E_MAX * HEADS];
__device__ float g_aesum[HEADS];
__device__ float g_alpha[F_MAX * HEADS];
__device__ float g_ex   [F_MAX * HEADS];
__device__ float g_m    [N_MAX * HEADS];
__device__ float g_den  [N_MAX * HEADS];
__device__ float g_agg  [N_MAX * HD];
__device__ float g_onsite[N_MAX];
__device__ float g_coup  [E_MAX];
__device__ int   g_dna  [N_MAX];
__device__ int   g_loc  [N_MAX];

// ---------------- small helpers -------------------------------------------
__device__ __forceinline__ void atomicMaxF(float* addr, float val) {
    int* ia = (int*)addr;
    int old = *ia;
    while (__int_as_float(old) < val) {
        int assumed = old;
        old = atomicCAS(ia, assumed, __float_as_int(val));
        if (old == assumed) break;
    }
}

// ---------------- GNN kernels ----------------------------------------------
__global__ void k_init_h(const float* __restrict__ x, const float* __restrict__ w,
                         const float* __restrict__ b) {
    int n = blockIdx.x, t = threadIdx.x;
    float acc = b[t];
#pragma unroll
    for (int k = 0; k < 4; k++) acc = fmaf(x[n * 4 + k], w[k * HD + t], acc);
    g_h[n * HD + t] = acc;
}

__global__ void k_init_e(const float* __restrict__ ea, const float* __restrict__ w,
                         const float* __restrict__ b) {
    int n = blockIdx.x, t = threadIdx.x;
    float acc = b[t];
#pragma unroll
    for (int k = 0; k < 5; k++) acc = fmaf(ea[n * 5 + k], w[k * HD + t], acc);
    g_e[n * HD + t] = acc;
}

__global__ void k_zero(int N) {
    int i = blockIdx.x * blockDim.x + threadIdx.x;
    if (i < N * HD) g_agg[i] = 0.f;
    if (i < N * HEADS) { g_m[i] = -3.0e38f; g_den[i] = 0.f; }
    if (i < HEADS) g_aesum[i] = 0.f;
}

__global__ void k_xl(const float* __restrict__ W, const float* __restrict__ asrc,
                     const float* __restrict__ adst) {
    __shared__ float hrow[HD];
    int n = blockIdx.x, t = threadIdx.x;
    hrow[t] = g_h[n * HD + t];
    __syncthreads();
    float acc = 0.f;
#pragma unroll 8
    for (int k = 0; k < HD; k++) acc = fmaf(hrow[k], W[k * HD + t], acc);
    g_xl[n * HD + t] = acc;
    int head = t >> 5, lane = t & 31;
    float vs = acc * asrc[head * CDIM + lane];
    float vd = acc * adst[head * CDIM + lane];
#pragma unroll
    for (int o = 16; o > 0; o >>= 1) {
        vs += __shfl_down_sync(0xffffffffu, vs, o);
        vd += __shfl_down_sync(0xffffffffu, vd, o);
    }
    if (lane == 0) { g_ssrc[n * HEADS + head] = vs; g_sdst[n * HEADS + head] = vd; }
}

__global__ void k_ae(const float* __restrict__ We, const float* __restrict__ aedge,
                     int E) {
    __shared__ float erow[HD];
    int e = blockIdx.x, t = threadIdx.x;
    erow[t] = g_e[e * HD + t];
    __syncthreads();
    float acc = 0.f;
#pragma unroll 8
    for (int k = 0; k < HD; k++) acc = fmaf(erow[k], We[k * HD + t], acc);
    int head = t >> 5, lane = t & 31;
    float v = acc * aedge[head * CDIM + lane];
#pragma unroll
    for (int o = 16; o > 0; o >>= 1) v += __shfl_down_sync(0xffffffffu, v, o);
    if (lane == 0) {
        g_ae[e * HEADS + head] = v;
        atomicAdd(&g_aesum[head], v);
    }
}

__global__ void k_alpha(const int* __restrict__ src, const int* __restrict__ dst,
                        int N, int E) {
    int idx = blockIdx.x * blockDim.x + threadIdx.x;
    int F = E + N;
    if (idx >= F * HEADS) return;
    int f = idx >> 2, hh = idx & 3;
    int s, d; float ae;
    if (f < E) { s = src[f]; d = dst[f]; ae = g_ae[f * HEADS + hh]; }
    else       { s = f - E; d = s;       ae = g_aesum[hh] / (float)E; }
    float a = g_ssrc[s * HEADS + hh] + g_sdst[d * HEADS + hh] + ae;
    a = a > 0.f ? a : 0.2f * a;
    g_alpha[idx] = a;
    atomicMaxF(&g_m[d * HEADS + hh], a);
}

__global__ void k_ex(const int* __restrict__ dst, int N, int E) {
    int idx = blockIdx.x * blockDim.x + threadIdx.x;
    int F = E + N;
    if (idx >= F * HEADS) return;
    int f = idx >> 2, hh = idx & 3;
    int d = (f < E) ? dst[f] : (f - E);
    float ex = expf(g_alpha[idx] - g_m[d * HEADS + hh]);
    g_ex[idx] = ex;
    atomicAdd(&g_den[d * HEADS + hh], ex);
}

__global__ void k_agg(const int* __restrict__ src, const int* __restrict__ dst,
                      int N, int E) {
    int f = blockIdx.x, t = threadIdx.x;
    int s, d;
    if (f < E) { s = src[f]; d = dst[f]; }
    else       { s = f - E;  d = s; }
    int hh = t >> 5;
    float w = g_ex[f * HEADS + hh] / g_den[d * HEADS + hh];
    atomicAdd(&g_agg[d * HD + t], g_xl[s * HD + t] * w);
}

__global__ void k_ln(const float* __restrict__ bias, const float* __restrict__ s,
                     const float* __restrict__ bb) {
    __shared__ float red[HD];
    int n = blockIdx.x, t = threadIdx.x;
    float v = g_agg[n * HD + t] + bias[t];
    v = v > 0.f ? v : 0.f;
    v += g_h[n * HD + t];
    red[t] = v; __syncthreads();
#pragma unroll
    for (int o = 64; o > 0; o >>= 1) { if (t < o) red[t] += red[t + o]; __syncthreads(); }
    float mu = red[0] / (float)HD;
    __syncthreads();
    float dd = v - mu;
    red[t] = dd * dd; __syncthreads();
#pragma unroll
    for (int o = 64; o > 0; o >>= 1) { if (t < o) red[t] += red[t + o]; __syncthreads(); }
    float var = red[0] / (float)HD;
    g_h[n * HD + t] = dd * rsqrtf(var + 1e-5f) * s[t] + bb[t];
}

// onsite (nodes) + coupling (edges) MLPs: 128 -> 64 (relu) -> 1
__global__ void k_mlp(const float* __restrict__ w1, const float* __restrict__ b1,
                      const float* __restrict__ w2, const float* __restrict__ b2,
                      const float* __restrict__ cw1, const float* __restrict__ cb1,
                      const float* __restrict__ cw2, const float* __restrict__ cb2,
                      int N) {
    __shared__ float in[HD];
    __shared__ float red[64];
    int blk = blockIdx.x, t = threadIdx.x;
    const float *row, *W1, *B1, *W2, *B2;
    if (blk < N) { row = &g_h[blk * HD];        W1 = w1;  B1 = b1;  W2 = w2;  B2 = b2;  }
    else         { row = &g_e[(blk - N) * HD];  W1 = cw1; B1 = cb1; W2 = cw2; B2 = cb2; }
    in[t] = row[t]; in[t + 64] = row[t + 64];
    __syncthreads();
    float acc = B1[t];
#pragma unroll 8
    for (int k = 0; k < HD; k++) acc = fmaf(in[k], W1[k * 64 + t], acc);
    acc = acc > 0.f ? acc : 0.f;
    red[t] = acc * W2[t];
    __syncthreads();
#pragma unroll
    for (int o = 32; o > 0; o >>= 1) { if (t < o) red[t] += red[t + o]; __syncthreads(); }
    if (t == 0) {
        float o = red[0] + B2[0];
        if (blk < N) g_onsite[blk] = o; else g_coup[blk - N] = o;
    }
}

// dna mask + local dna-index per graph (serial scan over <=2048 nodes in smem)
__global__ void k_dna(const float* __restrict__ x, const int* __restrict__ batch, int N) {
    __shared__ int mi[N_MAX];
    __shared__ int bt[N_MAX];
    __shared__ int lo[N_MAX];
    int t = threadIdx.x;
    for (int n = t; n < N; n += blockDim.x) {
        float a = x[n * 4], b = x[n * 4 + 1], c = x[n * 4 + 2], d = x[n * 4 + 3];
        int dna = (a != 0.f || b != 0.f || c != 0.f || d != 0.f) ? 1 : 0;
        mi[n] = dna;
        g_dna[n] = dna;
        bt[n] = batch[n];
    }
    __syncthreads();
    if (t == 0) {
        int cum = 0, curb = -1, gstart = 0;
        for (int n = 0; n < N; n++) {
            int b = bt[n];
            if (b != curb) { curb = b; gstart = cum; }
            lo[n] = cum - gstart;
            cum += mi[n];
        }
    }
    __syncthreads();
    for (int n = t; n < N; n += blockDim.x) g_loc[n] = lo[n];
}

__global__ void k_hinit(float* __restrict__ H, int B) {
    int idx = blockIdx.x * blockDim.x + threadIdx.x;
    if (idx >= B * HS * HS) return;
    int r = (idx % (HS * HS)) / HS, c = idx % HS;
    H[idx] = (r == c) ? 1e-6f : 0.f;
}

__global__ void k_hdiag(const int* __restrict__ batch, float* __restrict__ H, int N) {
    int n = blockIdx.x * blockDim.x + threadIdx.x;
    if (n >= N) return;
    if (g_dna[n]) {
        int b = batch[n], l = g_loc[n];
        H[b * HS * HS + l * HS + l] += g_onsite[n];
    }
}

__global__ void k_hedge(const int* __restrict__ src, const int* __restrict__ dst,
                        const int* __restrict__ batch, float* __restrict__ H, int E) {
    int e = blockIdx.x * blockDim.x + threadIdx.x;
    if (e >= E) return;
    int s = src[e], d = dst[e];
    if (g_dna[s] && g_dna[d]) {
        int b = batch[s], u = g_loc[s], v = g_loc[d];
        float cv = g_coup[e];
        atomicAdd(&H[b * HS * HS + u * HS + v], cv);
        atomicAdd(&H[b * HS * HS + v * HS + u], cv);
    }
}

// ---------------- NEGF: one CTA per (graph, energy) ------------------------
// smem: W = augmented [128 x 256] (A | I) -> (I | A_inv); C = 128x128 A_inv copy
#define SMEM_NEGF ((HS * 256 + HS * HS) * (int)sizeof(float))

__device__ __forceinline__ void gj_inverse(float* W, int tid,
                                           float* wred, int* widx, int* s_p,
                                           float* colbuf) {
    int warp = tid >> 5, lane = tid & 31;
    for (int k = 0; k < HS; k++) {
        // partial pivot: argmax |W[i][k]| for i >= k (threads 0..127)
        float v = -1.f; int myi = tid;
        if (tid < HS && tid >= k) v = fabsf(W[tid * 256 + k]);
#pragma unroll
        for (int o = 16; o > 0; o >>= 1) {
            float ov = __shfl_xor_sync(0xffffffffu, v, o);
            int   oi = __shfl_xor_sync(0xffffffffu, myi, o);
            if (ov > v) { v = ov; myi = oi; }
        }
        if (lane == 0) { wred[warp] = v; widx[warp] = myi; }
        __syncthreads();
        if (tid == 0) {
            float bv = wred[0]; int bi = widx[0];
            for (int w = 1; w < 4; w++) if (wred[w] > bv) { bv = wred[w]; bi = widx[w]; }
            *s_p = bi;
        }
        __syncthreads();
        int p = *s_p;
        if (p != k) {
            float a = W[k * 256 + tid], b = W[p * 256 + tid];
            W[k * 256 + tid] = b; W[p * 256 + tid] = a;
        }
        __syncthreads();
        float rowv = W[k * 256 + tid];
        float piv  = W[k * 256 + k];
        float pr = rowv / piv;
        __syncthreads();
        W[k * 256 + tid] = pr;
        if (tid < HS) colbuf[tid] = (tid == k) ? 0.f : W[tid * 256 + k];
        __syncthreads();
        float* Wc = W + tid;
#pragma unroll 4
        for (int i = 0; i < HS; i++) {
            Wc[i * 256] = fmaf(-colbuf[i], pr, Wc[i * 256]);
        }
        __syncthreads();
    }
}

__global__ void __launch_bounds__(256, 1) k_negf(
    const float* __restrict__ GL, const float* __restrict__ GR,
    const float* __restrict__ Hout, float* __restrict__ Tout,
    float* __restrict__ Dout) {
    extern __shared__ float sm[];
    float* W = sm;                 // 128*256
    float* C = sm + HS * 256;      // 128*128
    __shared__ float dv[HS];
    __shared__ float colbuf[HS];
    __shared__ float wred[8]; __shared__ int widx[8];
    __shared__ int s_p;
    __shared__ float rsum[8], rtr[8];

    int tid = threadIdx.x;
    int b = blockIdx.x / NEG, ei = blockIdx.x % NEG;
    float Eg = (float)(-3.0 + 6.0 * (double)ei / 99.0);
    const float* Hb = Hout + (size_t)b * HS * HS;

    for (int i = tid; i < HS; i += 256)
        dv[i] = 0.5f * (GL[b * HS + i] + GR[b * HS + i]) + 1e-12f;

    // augmented [A | I], A = Eg*I - H
    for (int idx = tid; idx < HS * 256; idx += 256) {
        int i = idx >> 8, j = idx & 255;
        float v;
        if (j < HS) v = ((i == j) ? Eg : 0.f) - Hb[i * HS + j];
        else        v = (j - HS == i) ? 1.f : 0.f;
        W[idx] = v;
    }
    __syncthreads();
    gj_inverse(W, tid, wred, widx, &s_p, colbuf);   // right half = A_inv

    for (int idx = tid; idx < HS * HS; idx += 256) {
        int i = idx >> 7, j = idx & 127;
        C[idx] = W[i * 256 + HS + j];
    }
    __syncthreads();

    // augmented [M | I], M = A + D A_inv D
    for (int idx = tid; idx < HS * 256; idx += 256) {
        int i = idx >> 8, j = idx & 255;
        float v;
        if (j < HS) {
            float a = ((i == j) ? Eg : 0.f) - Hb[i * HS + j];
            v = fmaf(dv[i] * C[i * HS + j], dv[j], a);
        } else v = (j - HS == i) ? 1.f : 0.f;
        W[idx] = v;
    }
    __syncthreads();
    gj_inverse(W, tid, wred, widx, &s_p, colbuf);   // right half = Gr_real

    // C := A_inv * D (column scale)
    for (int idx = tid; idx < HS * HS; idx += 256) C[idx] *= dv[idx & 127];
    __syncthreads();

    // Gr_imag = -C @ Gr_real, accumulate trace(Gr_imag) and
    // T = sum_ij GL_i (GrR^2 + GrI^2) GR_j
    float tsum = 0.f, trsum = 0.f;
    int warp = tid >> 5, lane = tid & 31;
    int j0 = lane * 4;
    float q0 = GR[b * HS + j0], q1 = GR[b * HS + j0 + 1];
    float q2 = GR[b * HS + j0 + 2], q3 = GR[b * HS + j0 + 3];
    for (int it = 0; it < 16; ++it) {
        int i = warp + it * 8;
        float gli = GL[b * HS + i];
        float a0 = 0.f, a1 = 0.f, a2 = 0.f, a3 = 0.f;
        const float* Ci = C + i * HS;
#pragma unroll 4
        for (int k = 0; k < HS; k++) {
            float bk = Ci[k];
            float4 g = *(const float4*)&W[k * 256 + HS + j0];
            a0 = fmaf(-bk, g.x, a0); a1 = fmaf(-bk, g.y, a1);
            a2 = fmaf(-bk, g.z, a2); a3 = fmaf(-bk, g.w, a3);
        }
        float4 gr = *(const float4*)&W[i * 256 + HS + j0];
        tsum += gli * (q0 * (gr.x * gr.x + a0 * a0) + q1 * (gr.y * gr.y + a1 * a1) +
                       q2 * (gr.z * gr.z + a2 * a2) + q3 * (gr.w * gr.w + a3 * a3));
        int dj = i - j0;
        if (dj >= 0 && dj < 4)
            trsum += (dj == 0) ? a0 : (dj == 1) ? a1 : (dj == 2) ? a2 : a3;
    }
#pragma unroll
    for (int o = 16; o > 0; o >>= 1) {
        tsum  += __shfl_down_sync(0xffffffffu, tsum, o);
        trsum += __shfl_down_sync(0xffffffffu, trsum, o);
    }
    if (lane == 0) { rsum[warp] = tsum; rtr[warp] = trsum; }
    __syncthreads();
    if (tid == 0) {
        float ts = 0.f, tr = 0.f;
        for (int w = 0; w < 8; w++) { ts += rsum[w]; tr += rtr[w]; }
        Tout[b * NEG + ei] = log10f(fmaxf(ts, 1e-16f));
        Dout[b * NEG + ei] = log10f(fmaxf(-tr / 3.14159265358979323846f, 1e-16f));
    }
}

// ---------------- launch ----------------------------------------------------
extern "C" void kernel_launch(void* const* d_in, const int* in_sizes, int n_in,
                              void* d_out, int out_size) {
    const float* x      = (const float*)d_in[0];
    const int*   ei     = (const int*)  d_in[1];
    const float* ea     = (const float*)d_in[2];
    const int*   batch  = (const int*)  d_in[3];
    const float* GL     = (const float*)d_in[4];
    const float* GR     = (const float*)d_in[5];
    const float* node_w = (const float*)d_in[6];
    const float* node_b = (const float*)d_in[7];
    const float* edgep_w= (const float*)d_in[8];
    const float* edgep_b= (const float*)d_in[9];
    const float* gat_lin= (const float*)d_in[10];
    const float* att_src= (const float*)d_in[11];
    const float* att_dst= (const float*)d_in[12];
    const float* gat_le = (const float*)d_in[13];
    const float* att_ed = (const float*)d_in[14];
    const float* gat_b  = (const float*)d_in[15];
    const float* ln_s   = (const float*)d_in[16];
    const float* ln_b   = (const float*)d_in[17];
    const float* on_w1  = (const float*)d_in[18];
    const float* on_b1  = (const float*)d_in[19];
    const float* on_w2  = (const float*)d_in[20];
    const float* on_b2  = (const float*)d_in[21];
    const float* cp_w1  = (const float*)d_in[22];
    const float* cp_b1  = (const float*)d_in[23];
    const float* cp_w2  = (const float*)d_in[24];
    const float* cp_b2  = (const float*)d_in[25];

    int N = in_sizes[0] / 4;
    int E = in_sizes[2] / 5;
    int B = in_sizes[4] / HS;
    const int* src = ei;
    const int* dst = ei + E;

    float* out  = (float*)d_out;
    float* Tout = out;
    float* Dout = out + B * NEG;
    float* Hout = out + 2 * B * NEG;

    k_init_h<<<N, HD>>>(x, node_w, node_b);
    k_init_e<<<E, HD>>>(ea, edgep_w, edgep_b);

    int F = (E + N) * HEADS;
    for (int l = 0; l < NLAYER; l++) {
        k_zero <<<(N * HD + 255) / 256, 256>>>(N);
        k_xl   <<<N, HD>>>(gat_lin + l * HD * HD, att_src + l * HEADS * CDIM,
                           att_dst + l * HEADS * CDIM);
        k_ae   <<<E, HD>>>(gat_le + l * HD * HD, att_ed + l * HEADS * CDIM, E);
        k_alpha<<<(F + 255) / 256, 256>>>(src, dst, N, E);
        k_ex   <<<(F + 255) / 256, 256>>>(dst, N, E);
        k_agg  <<<E + N, HD>>>(src, dst, N, E);
        k_ln   <<<N, HD>>>(gat_b + l * HD, ln_s + l * HD, ln_b + l * HD);
    }

    k_mlp  <<<N + E, 64>>>(on_w1, on_b1, on_w2, on_b2, cp_w1, cp_b1, cp_w2, cp_b2, N);
    k_dna  <<<1, 1024>>>(x, batch, N);
    k_hinit<<<(B * HS * HS + 255) / 256, 256>>>(Hout, B);
    k_hdiag<<<(N + 255) / 256, 256>>>(batch, Hout, N);
    k_hedge<<<(E + 255) / 256, 256>>>(src, dst, batch, Hout, E);

    cudaFuncSetAttribute(k_negf, cudaFuncAttributeMaxDynamicSharedMemorySize, SMEM_NEGF);
    k_negf<<<B * NEG, 256, SMEM_NEGF>>>(GL, GR, Hout, Tout, Dout);
}

// round 2
// speedup vs baseline: 1.6448x; 1.6448x over previous
#include <cuda_runtime.h>
#include <math.h>

#define HD     128
#define HEADS  4
#define CDIM   32
#define NLAYER 4
#define NEG    100
#define HS     128

#define N_MAX  2048
#define E_MAX  4096
#define F_MAX  (N_MAX + E_MAX)

// ---------------- scratch (device globals; no allocation allowed) ----------
__device__ float g_h   [N_MAX * HD];
__device__ float g_e   [E_MAX * HD];
__device__ float g_xl  [N_MAX * HD];
__device__ float g_ssrc[N_MAX * HEADS];
__device__ float g_sdst[N_MAX * HEADS];
__device__ float g_ae  [E_MAX * HEADS];
__device__ float g_aesum[HEADS];
__device__ float g_alpha[F_MAX * HEADS];
__device__ float g_ex   [F_MAX * HEADS];
__device__ float g_m    [N_MAX * HEADS];
__device__ float g_den  [N_MAX * HEADS];
__device__ float g_agg  [N_MAX * HD];
__device__ float g_onsite[N_MAX];
__device__ float g_coup  [E_MAX];
__device__ int   g_dna  [N_MAX];
__device__ int   g_loc  [N_MAX];

// ---------------- small helpers -------------------------------------------
__device__ __forceinline__ void atomicMaxF(float* addr, float val) {
    int* ia = (int*)addr;
    int old = *ia;
    while (__int_as_float(old) < val) {
        int assumed = old;
        old = atomicCAS(ia, assumed, __float_as_int(val));
        if (old == assumed) break;
    }
}

// ---------------- GNN kernels ----------------------------------------------
__global__ void k_init_h(const float* __restrict__ x, const float* __restrict__ w,
                         const float* __restrict__ b) {
    int n = blockIdx.x, t = threadIdx.x;
    float acc = b[t];
#pragma unroll
    for (int k = 0; k < 4; k++) acc = fmaf(x[n * 4 + k], w[k * HD + t], acc);
    g_h[n * HD + t] = acc;
}

__global__ void k_init_e(const float* __restrict__ ea, const float* __restrict__ w,
                         const float* __restrict__ b) {
    int n = blockIdx.x, t = threadIdx.x;
    float acc = b[t];
#pragma unroll
    for (int k = 0; k < 5; k++) acc = fmaf(ea[n * 5 + k], w[k * HD + t], acc);
    g_e[n * HD + t] = acc;
}

__global__ void k_zero(int N) {
    int i = blockIdx.x * blockDim.x + threadIdx.x;
    if (i < N * HD) g_agg[i] = 0.f;
    if (i < N * HEADS) { g_m[i] = -3.0e38f; g_den[i] = 0.f; }
    if (i < HEADS) g_aesum[i] = 0.f;
}

__global__ void k_xl(const float* __restrict__ W, const float* __restrict__ asrc,
                     const float* __restrict__ adst) {
    __shared__ float hrow[HD];
    int n = blockIdx.x, t = threadIdx.x;
    hrow[t] = g_h[n * HD + t];
    __syncthreads();
    float acc = 0.f;
#pragma unroll 8
    for (int k = 0; k < HD; k++) acc = fmaf(hrow[k], W[k * HD + t], acc);
    g_xl[n * HD + t] = acc;
    int head = t >> 5, lane = t & 31;
    float vs = acc * asrc[head * CDIM + lane];
    float vd = acc * adst[head * CDIM + lane];
#pragma unroll
    for (int o = 16; o > 0; o >>= 1) {
        vs += __shfl_down_sync(0xffffffffu, vs, o);
        vd += __shfl_down_sync(0xffffffffu, vd, o);
    }
    if (lane == 0) { g_ssrc[n * HEADS + head] = vs; g_sdst[n * HEADS + head] = vd; }
}

__global__ void k_ae(const float* __restrict__ We, const float* __restrict__ aedge,
                     int E) {
    __shared__ float erow[HD];
    int e = blockIdx.x, t = threadIdx.x;
    erow[t] = g_e[e * HD + t];
    __syncthreads();
    float acc = 0.f;
#pragma unroll 8
    for (int k = 0; k < HD; k++) acc = fmaf(erow[k], We[k * HD + t], acc);
    int head = t >> 5, lane = t & 31;
    float v = acc * aedge[head * CDIM + lane];
#pragma unroll
    for (int o = 16; o > 0; o >>= 1) v += __shfl_down_sync(0xffffffffu, v, o);
    if (lane == 0) {
        g_ae[e * HEADS + head] = v;
        atomicAdd(&g_aesum[head], v);
    }
}

__global__ void k_alpha(const int* __restrict__ src, const int* __restrict__ dst,
                        int N, int E) {
    int idx = blockIdx.x * blockDim.x + threadIdx.x;
    int F = E + N;
    if (idx >= F * HEADS) return;
    int f = idx >> 2, hh = idx & 3;
    int s, d; float ae;
    if (f < E) { s = src[f]; d = dst[f]; ae = g_ae[f * HEADS + hh]; }
    else       { s = f - E; d = s;       ae = g_aesum[hh] / (float)E; }
    float a = g_ssrc[s * HEADS + hh] + g_sdst[d * HEADS + hh] + ae;
    a = a > 0.f ? a : 0.2f * a;
    g_alpha[idx] = a;
    atomicMaxF(&g_m[d * HEADS + hh], a);
}

__global__ void k_ex(const int* __restrict__ dst, int N, int E) {
    int idx = blockIdx.x * blockDim.x + threadIdx.x;
    int F = E + N;
    if (idx >= F * HEADS) return;
    int f = idx >> 2, hh = idx & 3;
    int d = (f < E) ? dst[f] : (f - E);
    float ex = expf(g_alpha[idx] - g_m[d * HEADS + hh]);
    g_ex[idx] = ex;
    atomicAdd(&g_den[d * HEADS + hh], ex);
}

__global__ void k_agg(const int* __restrict__ src, const int* __restrict__ dst,
                      int N, int E) {
    int f = blockIdx.x, t = threadIdx.x;
    int s, d;
    if (f < E) { s = src[f]; d = dst[f]; }
    else       { s = f - E;  d = s; }
    int hh = t >> 5;
    float w = g_ex[f * HEADS + hh] / g_den[d * HEADS + hh];
    atomicAdd(&g_agg[d * HD + t], g_xl[s * HD + t] * w);
}

__global__ void k_ln(const float* __restrict__ bias, const float* __restrict__ s,
                     const float* __restrict__ bb) {
    __shared__ float red[HD];
    int n = blockIdx.x, t = threadIdx.x;
    float v = g_agg[n * HD + t] + bias[t];
    v = v > 0.f ? v : 0.f;
    v += g_h[n * HD + t];
    red[t] = v; __syncthreads();
#pragma unroll
    for (int o = 64; o > 0; o >>= 1) { if (t < o) red[t] += red[t + o]; __syncthreads(); }
    float mu = red[0] / (float)HD;
    __syncthreads();
    float dd = v - mu;
    red[t] = dd * dd; __syncthreads();
#pragma unroll
    for (int o = 64; o > 0; o >>= 1) { if (t < o) red[t] += red[t + o]; __syncthreads(); }
    float var = red[0] / (float)HD;
    g_h[n * HD + t] = dd * rsqrtf(var + 1e-5f) * s[t] + bb[t];
}

// onsite (nodes) + coupling (edges) MLPs: 128 -> 64 (relu) -> 1
__global__ void k_mlp(const float* __restrict__ w1, const float* __restrict__ b1,
                      const float* __restrict__ w2, const float* __restrict__ b2,
                      const float* __restrict__ cw1, const float* __restrict__ cb1,
                      const float* __restrict__ cw2, const float* __restrict__ cb2,
                      int N) {
    __shared__ float in[HD];
    __shared__ float red[64];
    int blk = blockIdx.x, t = threadIdx.x;
    const float *row, *W1, *B1, *W2, *B2;
    if (blk < N) { row = &g_h[blk * HD];        W1 = w1;  B1 = b1;  W2 = w2;  B2 = b2;  }
    else         { row = &g_e[(blk - N) * HD];  W1 = cw1; B1 = cb1; W2 = cw2; B2 = cb2; }
    in[t] = row[t]; in[t + 64] = row[t + 64];
    __syncthreads();
    float acc = B1[t];
#pragma unroll 8
    for (int k = 0; k < HD; k++) acc = fmaf(in[k], W1[k * 64 + t], acc);
    acc = acc > 0.f ? acc : 0.f;
    red[t] = acc * W2[t];
    __syncthreads();
#pragma unroll
    for (int o = 32; o > 0; o >>= 1) { if (t < o) red[t] += red[t + o]; __syncthreads(); }
    if (t == 0) {
        float o = red[0] + B2[0];
        if (blk < N) g_onsite[blk] = o; else g_coup[blk - N] = o;
    }
}

// dna mask + local dna-index per graph (serial scan over <=2048 nodes in smem)
__global__ void k_dna(const float* __restrict__ x, const int* __restrict__ batch, int N) {
    __shared__ int mi[N_MAX];
    __shared__ int bt[N_MAX];
    __shared__ int lo[N_MAX];
    int t = threadIdx.x;
    for (int n = t; n < N; n += blockDim.x) {
        float a = x[n * 4], b = x[n * 4 + 1], c = x[n * 4 + 2], d = x[n * 4 + 3];
        int dna = (a != 0.f || b != 0.f || c != 0.f || d != 0.f) ? 1 : 0;
        mi[n] = dna;
        g_dna[n] = dna;
        bt[n] = batch[n];
    }
    __syncthreads();
    if (t == 0) {
        int cum = 0, curb = -1, gstart = 0;
        for (int n = 0; n < N; n++) {
            int b = bt[n];
            if (b != curb) { curb = b; gstart = cum; }
            lo[n] = cum - gstart;
            cum += mi[n];
        }
    }
    __syncthreads();
    for (int n = t; n < N; n += blockDim.x) g_loc[n] = lo[n];
}

__global__ void k_hinit(float* __restrict__ H, int B) {
    int idx = blockIdx.x * blockDim.x + threadIdx.x;
    if (idx >= B * HS * HS) return;
    int r = (idx % (HS * HS)) / HS, c = idx % HS;
    H[idx] = (r == c) ? 1e-6f : 0.f;
}

__global__ void k_hdiag(const int* __restrict__ batch, float* __restrict__ H, int N) {
    int n = blockIdx.x * blockDim.x + threadIdx.x;
    if (n >= N) return;
    if (g_dna[n]) {
        int b = batch[n], l = g_loc[n];
        H[b * HS * HS + l * HS + l] += g_onsite[n];
    }
}

__global__ void k_hedge(const int* __restrict__ src, const int* __restrict__ dst,
                        const int* __restrict__ batch, float* __restrict__ H, int E) {
    int e = blockIdx.x * blockDim.x + threadIdx.x;
    if (e >= E) return;
    int s = src[e], d = dst[e];
    if (g_dna[s] && g_dna[d]) {
        int b = batch[s], u = g_loc[s], v = g_loc[d];
        float cv = g_coup[e];
        atomicAdd(&H[b * HS * HS + u * HS + v], cv);
        atomicAdd(&H[b * HS * HS + v * HS + u], cv);
    }
}

// ---------------- NEGF: one CTA per (graph, energy) ------------------------
// Gr = inv(A + i*D), single in-place complex Gauss-Jordan with row pivoting.
// W stored interleaved (float2), row stride 129 float2 to tame pivot-column
// bank conflicts. Column permutation unwound via index map at the end.
#define WSTRIDE 129
#define SMEM_NEGF (HS * WSTRIDE * (int)sizeof(float2))

__global__ void __launch_bounds__(256, 1) k_negf(
    const float* __restrict__ GL, const float* __restrict__ GR,
    const float* __restrict__ Hin, float* __restrict__ Tout,
    float* __restrict__ Dout) {
    extern __shared__ float2 W[];                  // [128][129]
    __shared__ float2 krow[HS];
    __shared__ float2 colbuf[HS];
    __shared__ float2 s_ip;
    __shared__ float  wred[4];
    __shared__ int    widx[4];
    __shared__ int    ipiv[HS];
    __shared__ int    s_arr[HS];
    __shared__ float  glv[HS], grv[HS];
    __shared__ float  rsum[8], rtr[8];

    int tid = threadIdx.x;
    int warp = tid >> 5, lane = tid & 31;
    int b = blockIdx.x / NEG, ei = blockIdx.x % NEG;
    float Eg = (float)(-3.0 + 6.0 * (double)ei / 99.0);
    const float* Hb = Hin + (size_t)b * HS * HS;

    if (tid < HS) {
        float gl = GL[b * HS + tid], gr = GR[b * HS + tid];
        glv[tid] = gl; grv[tid] = gr;
    }

    // W = A + i D, A = Eg*I - H, D = diag(0.5*(GL+GR) + 1e-12)
    for (int idx = tid; idx < HS * HS; idx += 256) {
        int i = idx >> 7, j = idx & 127;
        float re = ((i == j) ? Eg : 0.f) - Hb[idx];
        float im = (i == j) ? (0.5f * (GL[b * HS + i] + GR[b * HS + i]) + 1e-12f) : 0.f;
        W[i * WSTRIDE + j] = make_float2(re, im);
    }
    __syncthreads();

    int jcol = tid & 127;       // column owned in the update phase
    int half = tid >> 7;        // row half (0: rows 0-63, 1: rows 64-127)

    for (int k = 0; k < HS; k++) {
        // ---- pivot search: argmax_{i>=k} |W[i][k]|^2 (threads 0..127) ----
        if (tid < HS) {
            float2 wv = W[tid * WSTRIDE + k];
            float v = (tid >= k) ? fmaf(wv.x, wv.x, wv.y * wv.y) : -1.f;
            int myi = tid;
#pragma unroll
            for (int o = 16; o > 0; o >>= 1) {
                float ov = __shfl_xor_sync(0xffffffffu, v, o);
                int   oi = __shfl_xor_sync(0xffffffffu, myi, o);
                if (ov > v) { v = ov; myi = oi; }
            }
            if (lane == 0) { wred[warp] = v; widx[warp] = myi; }
        }
        __syncthreads();

        // ---- A1: everyone resolves r; read old rows k and r; compute 1/p ----
        float bv = wred[0]; int r = widx[0];
#pragma unroll
        for (int w = 1; w < 4; w++) if (wred[w] > bv) { bv = wred[w]; r = widx[w]; }
        float2 aj, bj, ci;
        if (tid < HS) {
            aj = W[k * WSTRIDE + tid];            // old row k
            bj = W[r * WSTRIDE + tid];            // pivot row (post-swap row k)
            int sg = (tid == r) ? k : tid;        // post-swap row index for colbuf
            ci = W[sg * WSTRIDE + k];
            if (tid == k) {
                float2 p = bj;                     // pivot = post-swap W[k][k]
                float inv = 1.f / fmaf(p.x, p.x, p.y * p.y);
                s_ip = make_float2(p.x * inv, -p.y * inv);
                ipiv[k] = r;
            }
        }
        __syncthreads();

        // ---- A2: write krow (scaled pivot row), colbuf, restore row r, zero col k
        float2 ip = s_ip;
        if (tid < HS) {
            float2 kr;
            if (tid == k) kr = ip;
            else kr = make_float2(bj.x * ip.x - bj.y * ip.y,
                                  bj.x * ip.y + bj.y * ip.x);
            krow[tid] = kr;
            colbuf[tid] = (tid == k) ? make_float2(0.f, 0.f) : ci;
            if (tid != k && r != k) W[r * WSTRIDE + tid] = aj;  // row r <- old row k
            W[tid * WSTRIDE + k] = make_float2(0.f, 0.f);       // zero column k
        }
        __syncthreads();

        // ---- C: rank-1 update, all 256 threads, 64 rows each -------------
        float2 kj = krow[jcol];
        float2* Wp = W + (half * 64) * WSTRIDE + jcol;
#pragma unroll 4
        for (int ii = 0; ii < 64; ii++) {
            int i = half * 64 + ii;
            float2 cv = colbuf[i];
            float2 m = Wp[ii * WSTRIDE];
            float mx = m.x - (cv.x * kj.x - cv.y * kj.y);
            float my = m.y - (cv.x * kj.y + cv.y * kj.x);
            if (i == k) { mx = kj.x; my = kj.y; }
            Wp[ii * WSTRIDE] = make_float2(mx, my);
        }
        __syncthreads();
    }

    // ---- unwind column permutation: true G[:, j] = W[:, arr[j]] ----------
    if (tid == 0) {
        for (int j = 0; j < HS; j++) s_arr[j] = j;
        for (int k = HS - 1; k >= 0; k--) {
            int r = ipiv[k];
            if (r != k) { int t = s_arr[k]; s_arr[k] = s_arr[r]; s_arr[r] = t; }
        }
    }
    __syncthreads();

    // ---- outputs: T = sum GL_i |G_ij|^2 GR_j ; dos from tr Im(G) ---------
    int c = s_arr[jcol];
    float wj = grv[jcol];
    float tpart = 0.f, dpart = 0.f;
#pragma unroll 4
    for (int ii = 0; ii < 64; ii++) {
        int i = half * 64 + ii;
        float2 g = W[i * WSTRIDE + c];
        tpart = fmaf(glv[i], fmaf(g.x, g.x, g.y * g.y), tpart);
    }
    tpart *= wj;
    if ((jcol >> 6) == half) dpart = W[jcol * WSTRIDE + c].y;  // Im G[j][j]
#pragma unroll
    for (int o = 16; o > 0; o >>= 1) {
        tpart += __shfl_down_sync(0xffffffffu, tpart, o);
        dpart += __shfl_down_sync(0xffffffffu, dpart, o);
    }
    if (lane == 0) { rsum[warp] = tpart; rtr[warp] = dpart; }
    __syncthreads();
    if (tid == 0) {
        float ts = 0.f, tr = 0.f;
#pragma unroll
        for (int w = 0; w < 8; w++) { ts += rsum[w]; tr += rtr[w]; }
        Tout[b * NEG + ei] = log10f(fmaxf(ts, 1e-16f));
        Dout[b * NEG + ei] = log10f(fmaxf(-tr / 3.14159265358979323846f, 1e-16f));
    }
}

// ---------------- launch ----------------------------------------------------
extern "C" void kernel_launch(void* const* d_in, const int* in_sizes, int n_in,
                              void* d_out, int out_size) {
    const float* x      = (const float*)d_in[0];
    const int*   ei     = (const int*)  d_in[1];
    const float* ea     = (const float*)d_in[2];
    const int*   batch  = (const int*)  d_in[3];
    const float* GL     = (const float*)d_in[4];
    const float* GR     = (const float*)d_in[5];
    const float* node_w = (const float*)d_in[6];
    const float* node_b = (const float*)d_in[7];
    const float* edgep_w= (const float*)d_in[8];
    const float* edgep_b= (const float*)d_in[9];
    const float* gat_lin= (const float*)d_in[10];
    const float* att_src= (const float*)d_in[11];
    const float* att_dst= (const float*)d_in[12];
    const float* gat_le = (const float*)d_in[13];
    const float* att_ed = (const float*)d_in[14];
    const float* gat_b  = (const float*)d_in[15];
    const float* ln_s   = (const float*)d_in[16];
    const float* ln_b   = (const float*)d_in[17];
    const float* on_w1  = (const float*)d_in[18];
    const float* on_b1  = (const float*)d_in[19];
    const float* on_w2  = (const float*)d_in[20];
    const float* on_b2  = (const float*)d_in[21];
    const float* cp_w1  = (const float*)d_in[22];
    const float* cp_b1  = (const float*)d_in[23];
    const float* cp_w2  = (const float*)d_in[24];
    const float* cp_b2  = (const float*)d_in[25];

    int N = in_sizes[0] / 4;
    int E = in_sizes[2] / 5;
    int B = in_sizes[4] / HS;
    const int* src = ei;
    const int* dst = ei + E;

    float* out  = (float*)d_out;
    float* Tout = out;
    float* Dout = out + B * NEG;
    float* Hout = out + 2 * B * NEG;

    k_init_h<<<N, HD>>>(x, node_w, node_b);
    k_init_e<<<E, HD>>>(ea, edgep_w, edgep_b);

    int F = (E + N) * HEADS;
    for (int l = 0; l < NLAYER; l++) {
        k_zero <<<(N * HD + 255) / 256, 256>>>(N);
        k_xl   <<<N, HD>>>(gat_lin + l * HD * HD, att_src + l * HEADS * CDIM,
                           att_dst + l * HEADS * CDIM);
        k_ae   <<<E, HD>>>(gat_le + l * HD * HD, att_ed + l * HEADS * CDIM, E);
        k_alpha<<<(F + 255) / 256, 256>>>(src, dst, N, E);
        k_ex   <<<(F + 255) / 256, 256>>>(dst, N, E);
        k_agg  <<<E + N, HD>>>(src, dst, N, E);
        k_ln   <<<N, HD>>>(gat_b + l * HD, ln_s + l * HD, ln_b + l * HD);
    }

    k_mlp  <<<N + E, 64>>>(on_w1, on_b1, on_w2, on_b2, cp_w1, cp_b1, cp_w2, cp_b2, N);
    k_dna  <<<1, 1024>>>(x, batch, N);
    k_hinit<<<(B * HS * HS + 255) / 256, 256>>>(Hout, B);
    k_hdiag<<<(N + 255) / 256, 256>>>(batch, Hout, N);
    k_hedge<<<(E + 255) / 256, 256>>>(src, dst, batch, Hout, E);

    cudaFuncSetAttribute(k_negf, cudaFuncAttributeMaxDynamicSharedMemorySize, SMEM_NEGF);
    k_negf<<<B * NEG, 256, SMEM_NEGF>>>(GL, GR, Hout, Tout, Dout);
}

// round 3
// speedup vs baseline: 4.2265x; 2.5695x over previous
#include <cuda_runtime.h>
#include <math.h>

#define HD     128
#define HEADS  4
#define CDIM   32
#define NLAYER 4
#define NEG    100
#define HS     128

#define N_MAX  2048
#define E_MAX  4096
#define F_MAX  (N_MAX + E_MAX)

// ---------------- scratch (device globals; no allocation allowed) ----------
__device__ float g_h   [N_MAX * HD];
__device__ float g_e   [E_MAX * HD];
__device__ float g_xl  [N_MAX * HD];
__device__ float g_ssrc[N_MAX * HEADS];
__device__ float g_sdst[N_MAX * HEADS];
__device__ float g_ae  [E_MAX * HEADS];
__device__ float g_aesum[HEADS];
__device__ float g_alpha[F_MAX * HEADS];
__device__ float g_ex   [F_MAX * HEADS];
__device__ float g_m    [N_MAX * HEADS];
__device__ float g_den  [N_MAX * HEADS];
__device__ float g_agg  [N_MAX * HD];
__device__ float g_onsite[N_MAX];
__device__ float g_coup  [E_MAX];
__device__ int   g_dna  [N_MAX];
__device__ int   g_loc  [N_MAX];

// ---------------- small helpers -------------------------------------------
__device__ __forceinline__ void atomicMaxF(float* addr, float val) {
    int* ia = (int*)addr;
    int old = *ia;
    while (__int_as_float(old) < val) {
        int assumed = old;
        old = atomicCAS(ia, assumed, __float_as_int(val));
        if (old == assumed) break;
    }
}

// ---------------- GNN kernels ----------------------------------------------
__global__ void k_init_h(const float* __restrict__ x, const float* __restrict__ w,
                         const float* __restrict__ b) {
    int n = blockIdx.x, t = threadIdx.x;
    float acc = b[t];
#pragma unroll
    for (int k = 0; k < 4; k++) acc = fmaf(x[n * 4 + k], w[k * HD + t], acc);
    g_h[n * HD + t] = acc;
}

__global__ void k_init_e(const float* __restrict__ ea, const float* __restrict__ w,
                         const float* __restrict__ b) {
    int n = blockIdx.x, t = threadIdx.x;
    float acc = b[t];
#pragma unroll
    for (int k = 0; k < 5; k++) acc = fmaf(ea[n * 5 + k], w[k * HD + t], acc);
    g_e[n * HD + t] = acc;
}

__global__ void k_zero(int N) {
    int i = blockIdx.x * blockDim.x + threadIdx.x;
    if (i < N * HD) g_agg[i] = 0.f;
    if (i < N * HEADS) { g_m[i] = -3.0e38f; g_den[i] = 0.f; }
    if (i < HEADS) g_aesum[i] = 0.f;
}

__global__ void k_xl(const float* __restrict__ W, const float* __restrict__ asrc,
                     const float* __restrict__ adst) {
    __shared__ float hrow[HD];
    int n = blockIdx.x, t = threadIdx.x;
    hrow[t] = g_h[n * HD + t];
    __syncthreads();
    float acc = 0.f;
#pragma unroll 8
    for (int k = 0; k < HD; k++) acc = fmaf(hrow[k], W[k * HD + t], acc);
    g_xl[n * HD + t] = acc;
    int head = t >> 5, lane = t & 31;
    float vs = acc * asrc[head * CDIM + lane];
    float vd = acc * adst[head * CDIM + lane];
#pragma unroll
    for (int o = 16; o > 0; o >>= 1) {
        vs += __shfl_down_sync(0xffffffffu, vs, o);
        vd += __shfl_down_sync(0xffffffffu, vd, o);
    }
    if (lane == 0) { g_ssrc[n * HEADS + head] = vs; g_sdst[n * HEADS + head] = vd; }
}

__global__ void k_ae(const float* __restrict__ We, const float* __restrict__ aedge,
                     int E) {
    __shared__ float erow[HD];
    int e = blockIdx.x, t = threadIdx.x;
    erow[t] = g_e[e * HD + t];
    __syncthreads();
    float acc = 0.f;
#pragma unroll 8
    for (int k = 0; k < HD; k++) acc = fmaf(erow[k], We[k * HD + t], acc);
    int head = t >> 5, lane = t & 31;
    float v = acc * aedge[head * CDIM + lane];
#pragma unroll
    for (int o = 16; o > 0; o >>= 1) v += __shfl_down_sync(0xffffffffu, v, o);
    if (lane == 0) {
        g_ae[e * HEADS + head] = v;
        atomicAdd(&g_aesum[head], v);
    }
}

__global__ void k_alpha(const int* __restrict__ src, const int* __restrict__ dst,
                        int N, int E) {
    int idx = blockIdx.x * blockDim.x + threadIdx.x;
    int F = E + N;
    if (idx >= F * HEADS) return;
    int f = idx >> 2, hh = idx & 3;
    int s, d; float ae;
    if (f < E) { s = src[f]; d = dst[f]; ae = g_ae[f * HEADS + hh]; }
    else       { s = f - E; d = s;       ae = g_aesum[hh] / (float)E; }
    float a = g_ssrc[s * HEADS + hh] + g_sdst[d * HEADS + hh] + ae;
    a = a > 0.f ? a : 0.2f * a;
    g_alpha[idx] = a;
    atomicMaxF(&g_m[d * HEADS + hh], a);
}

__global__ void k_ex(const int* __restrict__ dst, int N, int E) {
    int idx = blockIdx.x * blockDim.x + threadIdx.x;
    int F = E + N;
    if (idx >= F * HEADS) return;
    int f = idx >> 2, hh = idx & 3;
    int d = (f < E) ? dst[f] : (f - E);
    float ex = expf(g_alpha[idx] - g_m[d * HEADS + hh]);
    g_ex[idx] = ex;
    atomicAdd(&g_den[d * HEADS + hh], ex);
}

__global__ void k_agg(const int* __restrict__ src, const int* __restrict__ dst,
                      int N, int E) {
    int f = blockIdx.x, t = threadIdx.x;
    int s, d;
    if (f < E) { s = src[f]; d = dst[f]; }
    else       { s = f - E;  d = s; }
    int hh = t >> 5;
    float w = g_ex[f * HEADS + hh] / g_den[d * HEADS + hh];
    atomicAdd(&g_agg[d * HD + t], g_xl[s * HD + t] * w);
}

__global__ void k_ln(const float* __restrict__ bias, const float* __restrict__ s,
                     const float* __restrict__ bb) {
    __shared__ float red[HD];
    int n = blockIdx.x, t = threadIdx.x;
    float v = g_agg[n * HD + t] + bias[t];
    v = v > 0.f ? v : 0.f;
    v += g_h[n * HD + t];
    red[t] = v; __syncthreads();
#pragma unroll
    for (int o = 64; o > 0; o >>= 1) { if (t < o) red[t] += red[t + o]; __syncthreads(); }
    float mu = red[0] / (float)HD;
    __syncthreads();
    float dd = v - mu;
    red[t] = dd * dd; __syncthreads();
#pragma unroll
    for (int o = 64; o > 0; o >>= 1) { if (t < o) red[t] += red[t + o]; __syncthreads(); }
    float var = red[0] / (float)HD;
    g_h[n * HD + t] = dd * rsqrtf(var + 1e-5f) * s[t] + bb[t];
}

// onsite (nodes) + coupling (edges) MLPs: 128 -> 64 (relu) -> 1
__global__ void k_mlp(const float* __restrict__ w1, const float* __restrict__ b1,
                      const float* __restrict__ w2, const float* __restrict__ b2,
                      const float* __restrict__ cw1, const float* __restrict__ cb1,
                      const float* __restrict__ cw2, const float* __restrict__ cb2,
                      int N) {
    __shared__ float in[HD];
    __shared__ float red[64];
    int blk = blockIdx.x, t = threadIdx.x;
    const float *row, *W1, *B1, *W2, *B2;
    if (blk < N) { row = &g_h[blk * HD];        W1 = w1;  B1 = b1;  W2 = w2;  B2 = b2;  }
    else         { row = &g_e[(blk - N) * HD];  W1 = cw1; B1 = cb1; W2 = cw2; B2 = cb2; }
    in[t] = row[t]; in[t + 64] = row[t + 64];
    __syncthreads();
    float acc = B1[t];
#pragma unroll 8
    for (int k = 0; k < HD; k++) acc = fmaf(in[k], W1[k * 64 + t], acc);
    acc = acc > 0.f ? acc : 0.f;
    red[t] = acc * W2[t];
    __syncthreads();
#pragma unroll
    for (int o = 32; o > 0; o >>= 1) { if (t < o) red[t] += red[t + o]; __syncthreads(); }
    if (t == 0) {
        float o = red[0] + B2[0];
        if (blk < N) g_onsite[blk] = o; else g_coup[blk - N] = o;
    }
}

// dna mask + local dna-index per graph (serial scan over <=2048 nodes in smem)
__global__ void k_dna(const float* __restrict__ x, const int* __restrict__ batch, int N) {
    __shared__ int mi[N_MAX];
    __shared__ int bt[N_MAX];
    __shared__ int lo[N_MAX];
    int t = threadIdx.x;
    for (int n = t; n < N; n += blockDim.x) {
        float a = x[n * 4], b = x[n * 4 + 1], c = x[n * 4 + 2], d = x[n * 4 + 3];
        int dna = (a != 0.f || b != 0.f || c != 0.f || d != 0.f) ? 1 : 0;
        mi[n] = dna;
        g_dna[n] = dna;
        bt[n] = batch[n];
    }
    __syncthreads();
    if (t == 0) {
        int cum = 0, curb = -1, gstart = 0;
        for (int n = 0; n < N; n++) {
            int b = bt[n];
            if (b != curb) { curb = b; gstart = cum; }
            lo[n] = cum - gstart;
            cum += mi[n];
        }
    }
    __syncthreads();
    for (int n = t; n < N; n += blockDim.x) g_loc[n] = lo[n];
}

__global__ void k_hinit(float* __restrict__ H, int B) {
    int idx = blockIdx.x * blockDim.x + threadIdx.x;
    if (idx >= B * HS * HS) return;
    int r = (idx % (HS * HS)) / HS, c = idx % HS;
    H[idx] = (r == c) ? 1e-6f : 0.f;
}

__global__ void k_hdiag(const int* __restrict__ batch, float* __restrict__ H, int N) {
    int n = blockIdx.x * blockDim.x + threadIdx.x;
    if (n >= N) return;
    if (g_dna[n]) {
        int b = batch[n], l = g_loc[n];
        H[b * HS * HS + l * HS + l] += g_onsite[n];
    }
}

__global__ void k_hedge(const int* __restrict__ src, const int* __restrict__ dst,
                        const int* __restrict__ batch, float* __restrict__ H, int E) {
    int e = blockIdx.x * blockDim.x + threadIdx.x;
    if (e >= E) return;
    int s = src[e], d = dst[e];
    if (g_dna[s] && g_dna[d]) {
        int b = batch[s], u = g_loc[s], v = g_loc[d];
        float cv = g_coup[e];
        atomicAdd(&H[b * HS * HS + u * HS + v], cv);
        atomicAdd(&H[b * HS * HS + v * HS + u], cv);
    }
}

// ---------------- NEGF: one CTA per (graph, energy) ------------------------
// Gr = inv(A + i*D). Unpivoted complex Gauss-Jordan (valid: Im part of the
// matrix is positive definite => all Schur complements nonsingular).
// W stored as float4 (2 complex per slot), row stride 65 float4 (pad).
#define S4 65
#define S2 130
#define SMEM_NEGF (HS * S4 * (int)sizeof(float4))
#define NTHR 512

__global__ void __launch_bounds__(NTHR, 1) k_negf(
    const float* __restrict__ GL, const float* __restrict__ GR,
    const float* __restrict__ Hin, float* __restrict__ Tout,
    float* __restrict__ Dout) {
    extern __shared__ float4 W4[];          // [128][65] float4
    float2* W2 = (float2*)W4;               // same, [128][130] float2 view
    __shared__ float2 krow[HS];
    __shared__ float2 colbuf[HS];
    __shared__ float  glv[HS], grv[HS];
    __shared__ float  rsum[16], rtr[16];

    int tid = threadIdx.x;
    int warp = tid >> 5, lane = tid & 31;
    int b = blockIdx.x / NEG, ei = blockIdx.x % NEG;
    float Eg = (float)(-3.0 + 6.0 * (double)ei / 99.0);
    const float* Hb = Hin + (size_t)b * HS * HS;

    if (tid < HS) {
        glv[tid] = GL[b * HS + tid];
        grv[tid] = GR[b * HS + tid];
    }
    __syncthreads();

    // W = A + i D, A = Eg*I - H, D = diag(0.5*(GL+GR) + 1e-12)
    for (int idx = tid; idx < HS * HS; idx += NTHR) {
        int i = idx >> 7, j = idx & 127;
        float re = ((i == j) ? Eg : 0.f) - Hb[idx];
        float im = (i == j) ? (0.5f * (glv[i] + grv[i]) + 1e-12f) : 0.f;
        W2[i * S2 + j] = make_float2(re, im);
    }
    __syncthreads();

    int fc = tid & 63;          // float4 column (covers complex cols 2fc, 2fc+1)
    int rq = tid >> 6;          // row group 0..7 (16 rows each)
    float4* Wp = W4 + (rq * 16) * S4 + fc;

    for (int k = 0; k < HS; k++) {
        // ---- setup: krow = row k / pivot; colbuf = col k; zero col k ------
        if (tid < HS) {
            float2 pv = W2[k * S2 + k];
            float2 bj = W2[k * S2 + tid];
            float2 ci = W2[tid * S2 + k];
            float inv = 1.f / fmaf(pv.x, pv.x, pv.y * pv.y);
            float2 ip = make_float2(pv.x * inv, -pv.y * inv);
            float2 kr;
            if (tid == k) kr = ip;
            else kr = make_float2(bj.x * ip.x - bj.y * ip.y,
                                  bj.x * ip.y + bj.y * ip.x);
            krow[tid] = kr;
            colbuf[tid] = (tid == k) ? make_float2(0.f, 0.f) : ci;
            if (tid != k) W2[tid * S2 + k] = make_float2(0.f, 0.f);
        }
        __syncthreads();

        // ---- rank-1 update, float4 (2 complex) per thread-iteration -------
        float4 kj = *(const float4*)&krow[fc * 2];
        const float2* cb = colbuf + rq * 16;
#pragma unroll
        for (int ii = 0; ii < 16; ii++) {
            int i = rq * 16 + ii;
            float2 cv = cb[ii];
            float4 m = Wp[ii * S4];
            float mx0 = m.x - (cv.x * kj.x - cv.y * kj.y);
            float my0 = m.y - (cv.x * kj.y + cv.y * kj.x);
            float mx1 = m.z - (cv.x * kj.z - cv.y * kj.w);
            float my1 = m.w - (cv.x * kj.w + cv.y * kj.z);
            if (i == k) { mx0 = kj.x; my0 = kj.y; mx1 = kj.z; my1 = kj.w; }
            Wp[ii * S4] = make_float4(mx0, my0, mx1, my1);
        }
        __syncthreads();
    }

    // ---- outputs: T = sum_ij GL_i |G_ij|^2 GR_j ; dos = -tr(Im G)/pi ------
    int jcol = tid & 127;
    int q = tid >> 7;            // 0..3, 32 rows each
    float tpart = 0.f, dpart = 0.f;
#pragma unroll 4
    for (int ii = 0; ii < 32; ii++) {
        int i = q * 32 + ii;
        float2 g = W2[i * S2 + jcol];
        tpart = fmaf(glv[i], fmaf(g.x, g.x, g.y * g.y), tpart);
        if (i == jcol) dpart = g.y;
    }
    tpart *= grv[jcol];
#pragma unroll
    for (int o = 16; o > 0; o >>= 1) {
        tpart += __shfl_down_sync(0xffffffffu, tpart, o);
        dpart += __shfl_down_sync(0xffffffffu, dpart, o);
    }
    if (lane == 0) { rsum[warp] = tpart; rtr[warp] = dpart; }
    __syncthreads();
    if (tid == 0) {
        float ts = 0.f, tr = 0.f;
#pragma unroll
        for (int w = 0; w < 16; w++) { ts += rsum[w]; tr += rtr[w]; }
        Tout[b * NEG + ei] = log10f(fmaxf(ts, 1e-16f));
        Dout[b * NEG + ei] = log10f(fmaxf(-tr / 3.14159265358979323846f, 1e-16f));
    }
}

// ---------------- launch ----------------------------------------------------
extern "C" void kernel_launch(void* const* d_in, const int* in_sizes, int n_in,
                              void* d_out, int out_size) {
    const float* x      = (const float*)d_in[0];
    const int*   ei     = (const int*)  d_in[1];
    const float* ea     = (const float*)d_in[2];
    const int*   batch  = (const int*)  d_in[3];
    const float* GL     = (const float*)d_in[4];
    const float* GR     = (const float*)d_in[5];
    const float* node_w = (const float*)d_in[6];
    const float* node_b = (const float*)d_in[7];
    const float* edgep_w= (const float*)d_in[8];
    const float* edgep_b= (const float*)d_in[9];
    const float* gat_lin= (const float*)d_in[10];
    const float* att_src= (const float*)d_in[11];
    const float* att_dst= (const float*)d_in[12];
    const float* gat_le = (const float*)d_in[13];
    const float* att_ed = (const float*)d_in[14];
    const float* gat_b  = (const float*)d_in[15];
    const float* ln_s   = (const float*)d_in[16];
    const float* ln_b   = (const float*)d_in[17];
    const float* on_w1  = (const float*)d_in[18];
    const float* on_b1  = (const float*)d_in[19];
    const float* on_w2  = (const float*)d_in[20];
    const float* on_b2  = (const float*)d_in[21];
    const float* cp_w1  = (const float*)d_in[22];
    const float* cp_b1  = (const float*)d_in[23];
    const float* cp_w2  = (const float*)d_in[24];
    const float* cp_b2  = (const float*)d_in[25];

    int N = in_sizes[0] / 4;
    int E = in_sizes[2] / 5;
    int B = in_sizes[4] / HS;
    const int* src = ei;
    const int* dst = ei + E;

    float* out  = (float*)d_out;
    float* Tout = out;
    float* Dout = out + B * NEG;
    float* Hout = out + 2 * B * NEG;

    k_init_h<<<N, HD>>>(x, node_w, node_b);
    k_init_e<<<E, HD>>>(ea, edgep_w, edgep_b);

    int F = (E + N) * HEADS;
    for (int l = 0; l < NLAYER; l++) {
        k_zero <<<(N * HD + 255) / 256, 256>>>(N);
        k_xl   <<<N, HD>>>(gat_lin + l * HD * HD, att_src + l * HEADS * CDIM,
                           att_dst + l * HEADS * CDIM);
        k_ae   <<<E, HD>>>(gat_le + l * HD * HD, att_ed + l * HEADS * CDIM, E);
        k_alpha<<<(F + 255) / 256, 256>>>(src, dst, N, E);
        k_ex   <<<(F + 255) / 256, 256>>>(dst, N, E);
        k_agg  <<<E + N, HD>>>(src, dst, N, E);
        k_ln   <<<N, HD>>>(gat_b + l * HD, ln_s + l * HD, ln_b + l * HD);
    }

    k_mlp  <<<N + E, 64>>>(on_w1, on_b1, on_w2, on_b2, cp_w1, cp_b1, cp_w2, cp_b2, N);
    k_dna  <<<1, 1024>>>(x, batch, N);
    k_hinit<<<(B * HS * HS + 255) / 256, 256>>>(Hout, B);
    k_hdiag<<<(N + 255) / 256, 256>>>(batch, Hout, N);
    k_hedge<<<(E + 255) / 256, 256>>>(src, dst, batch, Hout, E);

    cudaFuncSetAttribute(k_negf, cudaFuncAttributeMaxDynamicSharedMemorySize, SMEM_NEGF);
    k_negf<<<B * NEG, NTHR, SMEM_NEGF>>>(GL, GR, Hout, Tout, Dout);
}

// round 4
// speedup vs baseline: 5.5407x; 1.3110x over previous
#include <cuda_runtime.h>
#include <math.h>

#define HD     128
#define HEADS  4
#define CDIM   32
#define NLAYER 4
#define NEG    100
#define HS     128

#define N_MAX  2048
#define E_MAX  4096
#define F_MAX  (N_MAX + E_MAX)

// ---------------- scratch (device globals; no allocation allowed) ----------
__device__ float g_h   [N_MAX * HD];
__device__ float g_e   [E_MAX * HD];
__device__ float g_xl  [N_MAX * HD];
__device__ float g_ssrc[N_MAX * HEADS];
__device__ float g_sdst[N_MAX * HEADS];
__device__ float g_ae  [E_MAX * HEADS];
__device__ float g_aesum[HEADS];
__device__ float g_alpha[F_MAX * HEADS];
__device__ float g_ex   [F_MAX * HEADS];
__device__ float g_m    [N_MAX * HEADS];
__device__ float g_den  [N_MAX * HEADS];
__device__ float g_agg  [N_MAX * HD];
__device__ float g_onsite[N_MAX];
__device__ float g_coup  [E_MAX];
__device__ int   g_dna  [N_MAX];
__device__ int   g_loc  [N_MAX];

// ---------------- small helpers -------------------------------------------
__device__ __forceinline__ void atomicMaxF(float* addr, float val) {
    int* ia = (int*)addr;
    int old = *ia;
    while (__int_as_float(old) < val) {
        int assumed = old;
        old = atomicCAS(ia, assumed, __float_as_int(val));
        if (old == assumed) break;
    }
}

// ---------------- GNN kernels ----------------------------------------------
__global__ void k_init_h(const float* __restrict__ x, const float* __restrict__ w,
                         const float* __restrict__ b) {
    int n = blockIdx.x, t = threadIdx.x;
    float acc = b[t];
#pragma unroll
    for (int k = 0; k < 4; k++) acc = fmaf(x[n * 4 + k], w[k * HD + t], acc);
    g_h[n * HD + t] = acc;
}

__global__ void k_init_e(const float* __restrict__ ea, const float* __restrict__ w,
                         const float* __restrict__ b) {
    int n = blockIdx.x, t = threadIdx.x;
    float acc = b[t];
#pragma unroll
    for (int k = 0; k < 5; k++) acc = fmaf(ea[n * 5 + k], w[k * HD + t], acc);
    g_e[n * HD + t] = acc;
}

__global__ void k_zero(int N) {
    int i = blockIdx.x * blockDim.x + threadIdx.x;
    if (i < N * HD) g_agg[i] = 0.f;
    if (i < N * HEADS) { g_m[i] = -3.0e38f; g_den[i] = 0.f; }
    if (i < HEADS) g_aesum[i] = 0.f;
}

__global__ void k_xl(const float* __restrict__ W, const float* __restrict__ asrc,
                     const float* __restrict__ adst) {
    __shared__ float hrow[HD];
    int n = blockIdx.x, t = threadIdx.x;
    hrow[t] = g_h[n * HD + t];
    __syncthreads();
    float acc = 0.f;
#pragma unroll 8
    for (int k = 0; k < HD; k++) acc = fmaf(hrow[k], W[k * HD + t], acc);
    g_xl[n * HD + t] = acc;
    int head = t >> 5, lane = t & 31;
    float vs = acc * asrc[head * CDIM + lane];
    float vd = acc * adst[head * CDIM + lane];
#pragma unroll
    for (int o = 16; o > 0; o >>= 1) {
        vs += __shfl_down_sync(0xffffffffu, vs, o);
        vd += __shfl_down_sync(0xffffffffu, vd, o);
    }
    if (lane == 0) { g_ssrc[n * HEADS + head] = vs; g_sdst[n * HEADS + head] = vd; }
}

__global__ void k_ae(const float* __restrict__ We, const float* __restrict__ aedge,
                     int E) {
    __shared__ float erow[HD];
    int e = blockIdx.x, t = threadIdx.x;
    erow[t] = g_e[e * HD + t];
    __syncthreads();
    float acc = 0.f;
#pragma unroll 8
    for (int k = 0; k < HD; k++) acc = fmaf(erow[k], We[k * HD + t], acc);
    int head = t >> 5, lane = t & 31;
    float v = acc * aedge[head * CDIM + lane];
#pragma unroll
    for (int o = 16; o > 0; o >>= 1) v += __shfl_down_sync(0xffffffffu, v, o);
    if (lane == 0) {
        g_ae[e * HEADS + head] = v;
        atomicAdd(&g_aesum[head], v);
    }
}

__global__ void k_alpha(const int* __restrict__ src, const int* __restrict__ dst,
                        int N, int E) {
    int idx = blockIdx.x * blockDim.x + threadIdx.x;
    int F = E + N;
    if (idx >= F * HEADS) return;
    int f = idx >> 2, hh = idx & 3;
    int s, d; float ae;
    if (f < E) { s = src[f]; d = dst[f]; ae = g_ae[f * HEADS + hh]; }
    else       { s = f - E; d = s;       ae = g_aesum[hh] / (float)E; }
    float a = g_ssrc[s * HEADS + hh] + g_sdst[d * HEADS + hh] + ae;
    a = a > 0.f ? a : 0.2f * a;
    g_alpha[idx] = a;
    atomicMaxF(&g_m[d * HEADS + hh], a);
}

__global__ void k_ex(const int* __restrict__ dst, int N, int E) {
    int idx = blockIdx.x * blockDim.x + threadIdx.x;
    int F = E + N;
    if (idx >= F * HEADS) return;
    int f = idx >> 2, hh = idx & 3;
    int d = (f < E) ? dst[f] : (f - E);
    float ex = expf(g_alpha[idx] - g_m[d * HEADS + hh]);
    g_ex[idx] = ex;
    atomicAdd(&g_den[d * HEADS + hh], ex);
}

__global__ void k_agg(const int* __restrict__ src, const int* __restrict__ dst,
                      int N, int E) {
    int f = blockIdx.x, t = threadIdx.x;
    int s, d;
    if (f < E) { s = src[f]; d = dst[f]; }
    else       { s = f - E;  d = s; }
    int hh = t >> 5;
    float w = g_ex[f * HEADS + hh] / g_den[d * HEADS + hh];
    atomicAdd(&g_agg[d * HD + t], g_xl[s * HD + t] * w);
}

__global__ void k_ln(const float* __restrict__ bias, const float* __restrict__ s,
                     const float* __restrict__ bb) {
    __shared__ float red[HD];
    int n = blockIdx.x, t = threadIdx.x;
    float v = g_agg[n * HD + t] + bias[t];
    v = v > 0.f ? v : 0.f;
    v += g_h[n * HD + t];
    red[t] = v; __syncthreads();
#pragma unroll
    for (int o = 64; o > 0; o >>= 1) { if (t < o) red[t] += red[t + o]; __syncthreads(); }
    float mu = red[0] / (float)HD;
    __syncthreads();
    float dd = v - mu;
    red[t] = dd * dd; __syncthreads();
#pragma unroll
    for (int o = 64; o > 0; o >>= 1) { if (t < o) red[t] += red[t + o]; __syncthreads(); }
    float var = red[0] / (float)HD;
    g_h[n * HD + t] = dd * rsqrtf(var + 1e-5f) * s[t] + bb[t];
}

// onsite (nodes) + coupling (edges) MLPs: 128 -> 64 (relu) -> 1
__global__ void k_mlp(const float* __restrict__ w1, const float* __restrict__ b1,
                      const float* __restrict__ w2, const float* __restrict__ b2,
                      const float* __restrict__ cw1, const float* __restrict__ cb1,
                      const float* __restrict__ cw2, const float* __restrict__ cb2,
                      int N) {
    __shared__ float in[HD];
    __shared__ float red[64];
    int blk = blockIdx.x, t = threadIdx.x;
    const float *row, *W1, *B1, *W2, *B2;
    if (blk < N) { row = &g_h[blk * HD];        W1 = w1;  B1 = b1;  W2 = w2;  B2 = b2;  }
    else         { row = &g_e[(blk - N) * HD];  W1 = cw1; B1 = cb1; W2 = cw2; B2 = cb2; }
    in[t] = row[t]; in[t + 64] = row[t + 64];
    __syncthreads();
    float acc = B1[t];
#pragma unroll 8
    for (int k = 0; k < HD; k++) acc = fmaf(in[k], W1[k * 64 + t], acc);
    acc = acc > 0.f ? acc : 0.f;
    red[t] = acc * W2[t];
    __syncthreads();
#pragma unroll
    for (int o = 32; o > 0; o >>= 1) { if (t < o) red[t] += red[t + o]; __syncthreads(); }
    if (t == 0) {
        float o = red[0] + B2[0];
        if (blk < N) g_onsite[blk] = o; else g_coup[blk - N] = o;
    }
}

// dna mask + local dna-index per graph (serial scan over <=2048 nodes in smem)
__global__ void k_dna(const float* __restrict__ x, const int* __restrict__ batch, int N) {
    __shared__ int mi[N_MAX];
    __shared__ int bt[N_MAX];
    __shared__ int lo[N_MAX];
    int t = threadIdx.x;
    for (int n = t; n < N; n += blockDim.x) {
        float a = x[n * 4], b = x[n * 4 + 1], c = x[n * 4 + 2], d = x[n * 4 + 3];
        int dna = (a != 0.f || b != 0.f || c != 0.f || d != 0.f) ? 1 : 0;
        mi[n] = dna;
        g_dna[n] = dna;
        bt[n] = batch[n];
    }
    __syncthreads();
    if (t == 0) {
        int cum = 0, curb = -1, gstart = 0;
        for (int n = 0; n < N; n++) {
            int b = bt[n];
            if (b != curb) { curb = b; gstart = cum; }
            lo[n] = cum - gstart;
            cum += mi[n];
        }
    }
    __syncthreads();
    for (int n = t; n < N; n += blockDim.x) g_loc[n] = lo[n];
}

__global__ void k_hinit(float* __restrict__ H, int B) {
    int idx = blockIdx.x * blockDim.x + threadIdx.x;
    if (idx >= B * HS * HS) return;
    int r = (idx % (HS * HS)) / HS, c = idx % HS;
    H[idx] = (r == c) ? 1e-6f : 0.f;
}

__global__ void k_hdiag(const int* __restrict__ batch, float* __restrict__ H, int N) {
    int n = blockIdx.x * blockDim.x + threadIdx.x;
    if (n >= N) return;
    if (g_dna[n]) {
        int b = batch[n], l = g_loc[n];
        H[b * HS * HS + l * HS + l] += g_onsite[n];
    }
}

__global__ void k_hedge(const int* __restrict__ src, const int* __restrict__ dst,
                        const int* __restrict__ batch, float* __restrict__ H, int E) {
    int e = blockIdx.x * blockDim.x + threadIdx.x;
    if (e >= E) return;
    int s = src[e], d = dst[e];
    if (g_dna[s] && g_dna[d]) {
        int b = batch[s], u = g_loc[s], v = g_loc[d];
        float cv = g_coup[e];
        atomicAdd(&H[b * HS * HS + u * HS + v], cv);
        atomicAdd(&H[b * HS * HS + v * HS + u], cv);
    }
}

// ---------------- NEGF: one CTA per (graph, energy) ------------------------
// Gr = inv(A + i*D). Rank-8 blocked, unpivoted complex Gauss-Jordan.
// W lives in registers: 512 threads, each owns 16 rows x 2 complex cols.
// Per block-step only the 8-wide panels (C, R) go through shared memory.
#define NB    8
#define NBLK  (HS / NB)
#define NTHR  512

// complex fma: m -= c * r
#define CFMS(m, c, r) do { \
    m.x = fmaf(-(c).x, (r).x, fmaf((c).y, (r).y, m.x)); \
    m.y = fmaf(-(c).x, (r).y, fmaf(-(c).y, (r).x, m.y)); \
} while (0)
// complex mul: out = a * b
#define CMUL(o, a, b) do { \
    o.x = (a).x * (b).x - (a).y * (b).y; \
    o.y = (a).x * (b).y + (a).y * (b).x; \
} while (0)

__global__ void __launch_bounds__(NTHR, 1) k_negf(
    const float* __restrict__ GL, const float* __restrict__ GR,
    const float* __restrict__ Hin, float* __restrict__ Tout,
    float* __restrict__ Dout) {
    __shared__ float2 Cs[HS][NB];       // column panel W[:,K]
    __shared__ float4 Rs[NB][64];       // row panel, packed col pairs
    __shared__ float2 Pb[NB][NB];       // 8x8 pivot block -> its inverse
    __shared__ float  glv[HS], grv[HS];
    __shared__ float  rsum[16], rtr[16];

    int tid  = threadIdx.x;
    int fc   = tid & 63;                // owns complex cols 2fc, 2fc+1
    int rq   = tid >> 6;                // owns rows rq*16 .. rq*16+15
    int warp = tid >> 5, lane = tid & 31;
    int b = blockIdx.x / NEG, ei = blockIdx.x % NEG;
    float Eg = (float)(-3.0 + 6.0 * (double)ei / 99.0);
    const float2* Hb2 = (const float2*)(Hin + (size_t)b * HS * HS);

    if (tid < HS) {
        glv[tid] = GL[b * HS + tid];
        grv[tid] = GR[b * HS + tid];
    }
    __syncthreads();

    // W = A + i*D in registers: w[ii][c] = elem (rq*16+ii, 2fc+c)
    float2 w[16][2];
#pragma unroll
    for (int ii = 0; ii < 16; ii++) {
        int i = rq * 16 + ii;
        float2 hv = Hb2[i * 64 + fc];
        float dvi = 0.5f * (glv[i] + grv[i]) + 1e-12f;
        int j0 = 2 * fc;
        w[ii][0] = make_float2(((i == j0)     ? Eg : 0.f) - hv.x,
                               (i == j0)     ? dvi : 0.f);
        w[ii][1] = make_float2(((i == j0 + 1) ? Eg : 0.f) - hv.y,
                               (i == j0 + 1) ? dvi : 0.f);
    }

    for (int kb = 0; kb < NBLK; kb++) {
        int c0 = kb * NB;
        bool blockcol = ((fc >> 2) == kb);      // owns cols inside block K

        // ---- phase 1: column panel C = W[:,K] -----------------------------
        if (blockcol) {
            int q0 = (fc & 3) * 2;
#pragma unroll
            for (int ii = 0; ii < 16; ii++) {
                int i = rq * 16 + ii;
                Cs[i][q0]     = w[ii][0];
                Cs[i][q0 + 1] = w[ii][1];
            }
        }
        __syncthreads();

        // ---- phase 2: Pinv (8x8) by warp 0 --------------------------------
        if (warp == 0) {
#pragma unroll
            for (int e2 = 0; e2 < 2; e2++) {
                int e = lane + e2 * 32;
                Pb[e >> 3][e & 7] = Cs[c0 + (e >> 3)][e & 7];
            }
            __syncwarp();
            for (int kk = 0; kk < NB; kk++) {
                float2 pv = Pb[kk][kk];
                float inv = 1.f / fmaf(pv.x, pv.x, pv.y * pv.y);
                float2 ip = make_float2(pv.x * inv, -pv.y * inv);
                float2 nv[2];
#pragma unroll
                for (int e2 = 0; e2 < 2; e2++) {
                    int e = lane + e2 * 32, r = e >> 3, c = e & 7;
                    float2 old  = Pb[r][c];
                    float2 rowk = Pb[kk][c];
                    float2 colk = Pb[r][kk];
                    if (r == kk && c == kk) nv[e2] = ip;
                    else if (r == kk)       { CMUL(nv[e2], rowk, ip); }
                    else if (c == kk) {
                        float2 t; CMUL(t, colk, ip);
                        nv[e2] = make_float2(-t.x, -t.y);
                    } else {
                        float2 kr; CMUL(kr, rowk, ip);
                        nv[e2] = old; CFMS(nv[e2], colk, kr);
                    }
                }
                __syncwarp();
#pragma unroll
                for (int e2 = 0; e2 < 2; e2++) {
                    int e = lane + e2 * 32;
                    Pb[e >> 3][e & 7] = nv[e2];
                }
                __syncwarp();
            }
        }
        __syncthreads();

        // ---- phase 3: row panel R = Pinv * Wold[K,:] ; R[:,K] = Pinv ------
        if (rq == (kb >> 1)) {
            int base = (kb & 1) * 8;                 // K rows within my tile
            if (blockcol) {
                int jj = (fc & 3) * 2;
#pragma unroll
                for (int q = 0; q < NB; q++) {
                    float2 a = Pb[q][jj], c = Pb[q][jj + 1];
                    Rs[q][fc] = make_float4(a.x, a.y, c.x, c.y);
                }
            } else {
#pragma unroll
                for (int q = 0; q < NB; q++) {
                    float2 a0 = make_float2(0.f, 0.f), a1 = make_float2(0.f, 0.f);
#pragma unroll
                    for (int p = 0; p < NB; p++) {
                        float2 pi = Pb[q][p];
                        float2 u0 = w[base + p][0], u1 = w[base + p][1];
                        a0.x = fmaf(pi.x, u0.x, fmaf(-pi.y, u0.y, a0.x));
                        a0.y = fmaf(pi.x, u0.y, fmaf( pi.y, u0.x, a0.y));
                        a1.x = fmaf(pi.x, u1.x, fmaf(-pi.y, u1.y, a1.x));
                        a1.y = fmaf(pi.x, u1.y, fmaf( pi.y, u1.x, a1.y));
                    }
                    Rs[q][fc] = make_float4(a0.x, a0.y, a1.x, a1.y);
                }
            }
        }
        __syncthreads();

        // ---- phase 4: rank-8 update on register tile ----------------------
        float4 r4[NB];
#pragma unroll
        for (int q = 0; q < NB; q++) r4[q] = Rs[q][fc];

#pragma unroll
        for (int ii = 0; ii < 16; ii++) {
            int i = rq * 16 + ii;
            if ((i >> 3) == kb) {                    // row inside K: assign R
                float4 rr = r4[i & 7];
                w[ii][0] = make_float2(rr.x, rr.y);
                w[ii][1] = make_float2(rr.z, rr.w);
            } else {
                float2 m0, m1;
                if (blockcol) { m0 = make_float2(0.f, 0.f); m1 = make_float2(0.f, 0.f); }
                else          { m0 = w[ii][0]; m1 = w[ii][1]; }
                const float4* crow = (const float4*)&Cs[i][0];
#pragma unroll
                for (int qq = 0; qq < 4; qq++) {
                    float4 cp = crow[qq];            // 2 complex C values
                    float2 ca = make_float2(cp.x, cp.y);
                    float2 cb = make_float2(cp.z, cp.w);
                    float4 ra = r4[qq * 2], rb = r4[qq * 2 + 1];
                    float2 ra0 = make_float2(ra.x, ra.y), ra1 = make_float2(ra.z, ra.w);
                    float2 rb0 = make_float2(rb.x, rb.y), rb1 = make_float2(rb.z, rb.w);
                    CFMS(m0, ca, ra0); CFMS(m1, ca, ra1);
                    CFMS(m0, cb, rb0); CFMS(m1, cb, rb1);
                }
                w[ii][0] = m0; w[ii][1] = m1;
            }
        }
        __syncthreads();   // panels reused next block-step
    }

    // ---- outputs: T = sum_ij GL_i |G_ij|^2 GR_j ; dos = -tr(Im G)/pi ------
    float tpart = 0.f, dpart = 0.f;
    int j0 = 2 * fc;
    float gr0 = grv[j0], gr1 = grv[j0 + 1];
#pragma unroll
    for (int ii = 0; ii < 16; ii++) {
        int i = rq * 16 + ii;
        float2 g0 = w[ii][0], g1 = w[ii][1];
        tpart += glv[i] * (gr0 * fmaf(g0.x, g0.x, g0.y * g0.y) +
                           gr1 * fmaf(g1.x, g1.x, g1.y * g1.y));
        if (i == j0)     dpart += g0.y;
        if (i == j0 + 1) dpart += g1.y;
    }
#pragma unroll
    for (int o = 16; o > 0; o >>= 1) {
        tpart += __shfl_down_sync(0xffffffffu, tpart, o);
        dpart += __shfl_down_sync(0xffffffffu, dpart, o);
    }
    if (lane == 0) { rsum[warp] = tpart; rtr[warp] = dpart; }
    __syncthreads();
    if (tid == 0) {
        float ts = 0.f, tr = 0.f;
#pragma unroll
        for (int ww = 0; ww < 16; ww++) { ts += rsum[ww]; tr += rtr[ww]; }
        Tout[b * NEG + ei] = log10f(fmaxf(ts, 1e-16f));
        Dout[b * NEG + ei] = log10f(fmaxf(-tr / 3.14159265358979323846f, 1e-16f));
    }
}

// ---------------- launch ----------------------------------------------------
extern "C" void kernel_launch(void* const* d_in, const int* in_sizes, int n_in,
                              void* d_out, int out_size) {
    const float* x      = (const float*)d_in[0];
    const int*   ei     = (const int*)  d_in[1];
    const float* ea     = (const float*)d_in[2];
    const int*   batch  = (const int*)  d_in[3];
    const float* GL     = (const float*)d_in[4];
    const float* GR     = (const float*)d_in[5];
    const float* node_w = (const float*)d_in[6];
    const float* node_b = (const float*)d_in[7];
    const float* edgep_w= (const float*)d_in[8];
    const float* edgep_b= (const float*)d_in[9];
    const float* gat_lin= (const float*)d_in[10];
    const float* att_src= (const float*)d_in[11];
    const float* att_dst= (const float*)d_in[12];
    const float* gat_le = (const float*)d_in[13];
    const float* att_ed = (const float*)d_in[14];
    const float* gat_b  = (const float*)d_in[15];
    const float* ln_s   = (const float*)d_in[16];
    const float* ln_b   = (const float*)d_in[17];
    const float* on_w1  = (const float*)d_in[18];
    const float* on_b1  = (const float*)d_in[19];
    const float* on_w2  = (const float*)d_in[20];
    const float* on_b2  = (const float*)d_in[21];
    const float* cp_w1  = (const float*)d_in[22];
    const float* cp_b1  = (const float*)d_in[23];
    const float* cp_w2  = (const float*)d_in[24];
    const float* cp_b2  = (const float*)d_in[25];

    int N = in_sizes[0] / 4;
    int E = in_sizes[2] / 5;
    int B = in_sizes[4] / HS;
    const int* src = ei;
    const int* dst = ei + E;

    float* out  = (float*)d_out;
    float* Tout = out;
    float* Dout = out + B * NEG;
    float* Hout = out + 2 * B * NEG;

    k_init_h<<<N, HD>>>(x, node_w, node_b);
    k_init_e<<<E, HD>>>(ea, edgep_w, edgep_b);

    int F = (E + N) * HEADS;
    for (int l = 0; l < NLAYER; l++) {
        k_zero <<<(N * HD + 255) / 256, 256>>>(N);
        k_xl   <<<N, HD>>>(gat_lin + l * HD * HD, att_src + l * HEADS * CDIM,
                           att_dst + l * HEADS * CDIM);
        k_ae   <<<E, HD>>>(gat_le + l * HD * HD, att_ed + l * HEADS * CDIM, E);
        k_alpha<<<(F + 255) / 256, 256>>>(src, dst, N, E);
        k_ex   <<<(F + 255) / 256, 256>>>(dst, N, E);
        k_agg  <<<E + N, HD>>>(src, dst, N, E);
        k_ln   <<<N, HD>>>(gat_b + l * HD, ln_s + l * HD, ln_b + l * HD);
    }

    k_mlp  <<<N + E, 64>>>(on_w1, on_b1, on_w2, on_b2, cp_w1, cp_b1, cp_w2, cp_b2, N);
    k_dna  <<<1, 1024>>>(x, batch, N);
    k_hinit<<<(B * HS * HS + 255) / 256, 256>>>(Hout, B);
    k_hdiag<<<(N + 255) / 256, 256>>>(batch, Hout, N);
    k_hedge<<<(E + 255) / 256, 256>>>(src, dst, batch, Hout, E);

    k_negf<<<B * NEG, NTHR>>>(GL, GR, Hout, Tout, Dout);
}